// round 16
// baseline (speedup 1.0000x reference)
#include <cuda_runtime.h>
#include <cuda_bf16.h>
#include <stdint.h>

#define Hh   256
#define Bb   64
#define LPp  2048
#define LQq  64
#define D2   512
#define G3   1536

// ---------------- device scratch (no allocations allowed) ----------------
struct Scratch {
    float passP[LPp * Bb * Hh];   // [ (p*64+b) ][256]
    float quesP[LQq * Bb * Hh];   // [ (q*64+b) ][256]
    float biasQ[Hh];
    float sQ[Bb * LQq];           // [b][q]
    float rQ[Bb * D2];
    float rQ2[Bb * D2];
    float uah[Bb * Hh];
    float sP[Bb * LPp];           // [b][p] (reused in-place as aP)
    float ct[Bb * D2];
    float part[16 * Bb * D2];
    float gi[Bb * G3];
    float gh[Bb * G3];
};
__device__ Scratch g_s;

// ---------------- helpers ----------------
__device__ __forceinline__ unsigned f2tf32(float f) {
    unsigned r; asm("cvt.rna.tf32.f32 %0, %1;" : "=r"(r) : "f"(f)); return r;
}
__device__ __forceinline__ void mma8(float* c, unsigned a0, unsigned a1, unsigned a2,
                                     unsigned a3, unsigned b0, unsigned b1) {
    asm volatile(
        "mma.sync.aligned.m16n8k8.row.col.f32.tf32.tf32.f32 "
        "{%0,%1,%2,%3}, {%4,%5,%6,%7}, {%8,%9}, {%0,%1,%2,%3};"
        : "+f"(c[0]), "+f"(c[1]), "+f"(c[2]), "+f"(c[3])
        : "r"(a0), "r"(a1), "r"(a2), "r"(a3), "r"(b0), "r"(b1));
}
__device__ __forceinline__ void cp16(float* s, const float* g) {
    unsigned sa = (unsigned)__cvta_generic_to_shared(s);
    asm volatile("cp.async.cg.shared.global [%0], [%1], 16;" :: "r"(sa), "l"(g));
}

// ---------------- K0: biasQ = WQu_b + WQv_b + WQv_W @ VQr ----------------
__global__ void biasq_kernel(const float* __restrict__ WQv_W, const float* __restrict__ WQv_b,
                             const float* __restrict__ WQu_b, const float* __restrict__ VQr) {
    __shared__ float v[256];
    int tid = threadIdx.x;
    v[tid] = VQr[tid];
    __syncthreads();
    float acc = WQv_b[tid] + WQu_b[tid];
    const float* w = WQv_W + tid * 256;
    #pragma unroll 8
    for (int k = 0; k < 256; ++k) acc += w[k] * v[k];
    g_s.biasQ[tid] = acc;
}

// ---------------- tf32 GEMM: C[r][n] = A[r][:512] . W[n][:512] + bias[n] ----
// M = grid.x*64, N=256, K=512. BM=64, BN=256, BK=32. 256 thr = 8 warps (2x4).
#define SROW 36
#define A_WORDS (64 * SROW)
#define W_WORDS (256 * SROW)
#define BUFW (A_WORDS + W_WORDS)
#define GEMM_SMEM (2 * BUFW * 4)

__global__ __launch_bounds__(256, 1)
void gemm_tf32(const float* __restrict__ A, const float* __restrict__ W,
               const float* __restrict__ bias, float* __restrict__ C) {
    extern __shared__ float sm[];
    const int tid = threadIdx.x;
    const int lane = tid & 31, wid = tid >> 5;
    const int g = lane >> 2, t = lane & 3;
    const int warp_m = wid & 1;     // rows warp_m*32 .. +31
    const int warp_n = wid >> 1;    // cols warp_n*64 .. +63
    const size_t r0 = (size_t)blockIdx.x * 64;
    const float* Ag = A + r0 * 512;

    float acc[2][8][4];
    #pragma unroll
    for (int i = 0; i < 2; i++)
        #pragma unroll
        for (int j = 0; j < 8; j++) {
            acc[i][j][0] = 0.f; acc[i][j][1] = 0.f; acc[i][j][2] = 0.f; acc[i][j][3] = 0.f;
        }

    auto issue = [&](int kc, int buf) {
        float* As = sm + buf * BUFW;
        float* Ws = As + A_WORDS;
        const int k0 = kc * 32;
        #pragma unroll
        for (int i = 0; i < 2; i++) {
            int idx = tid + i * 256; int row = idx >> 3, c4 = idx & 7;
            cp16(As + row * SROW + c4 * 4, Ag + (size_t)row * 512 + k0 + c4 * 4);
        }
        #pragma unroll
        for (int i = 0; i < 8; i++) {
            int idx = tid + i * 256; int row = idx >> 3, c4 = idx & 7;
            cp16(Ws + row * SROW + c4 * 4, W + (size_t)row * 512 + k0 + c4 * 4);
        }
        asm volatile("cp.async.commit_group;");
    };

    issue(0, 0);

    for (int kc = 0; kc < 16; kc++) {
        const int cur = kc & 1;
        if (kc + 1 < 16) {
            issue(kc + 1, cur ^ 1);
            asm volatile("cp.async.wait_group 1;");
        } else {
            asm volatile("cp.async.wait_group 0;");
        }
        __syncthreads();

        const float* Ab = sm + cur * BUFW;
        const float* Wb = Ab + A_WORDS;
        #pragma unroll
        for (int ks = 0; ks < 4; ks++) {
            const int kb = ks * 8;
            unsigned a[2][4];
            #pragma unroll
            for (int mt = 0; mt < 2; mt++) {
                int row = warp_m * 32 + mt * 16 + g;
                a[mt][0] = f2tf32(Ab[row * SROW + kb + t]);
                a[mt][1] = f2tf32(Ab[(row + 8) * SROW + kb + t]);
                a[mt][2] = f2tf32(Ab[row * SROW + kb + t + 4]);
                a[mt][3] = f2tf32(Ab[(row + 8) * SROW + kb + t + 4]);
            }
            #pragma unroll
            for (int nt = 0; nt < 8; nt++) {
                int n = warp_n * 64 + nt * 8 + g;
                unsigned b0 = f2tf32(Wb[n * SROW + kb + t]);
                unsigned b1 = f2tf32(Wb[n * SROW + kb + t + 4]);
                mma8(acc[0][nt], a[0][0], a[0][1], a[0][2], a[0][3], b0, b1);
                mma8(acc[1][nt], a[1][0], a[1][1], a[1][2], a[1][3], b0, b1);
            }
        }
        __syncthreads();
    }

    // epilogue
    #pragma unroll
    for (int mt = 0; mt < 2; mt++) {
        #pragma unroll
        for (int nt = 0; nt < 8; nt++) {
            size_t row = r0 + warp_m * 32 + mt * 16 + g;
            int col = warp_n * 64 + nt * 8 + 2 * t;
            float b0 = bias[col], b1 = bias[col + 1];
            C[row * 256 + col]       = acc[mt][nt][0] + b0;
            C[row * 256 + col + 1]   = acc[mt][nt][1] + b1;
            C[(row + 8) * 256 + col]     = acc[mt][nt][2] + b0;
            C[(row + 8) * 256 + col + 1] = acc[mt][nt][3] + b1;
        }
    }
}

// ---------------- tanh-dot: S[b][l] = sum_h tanh(P[r][h] + add[b][h]) * Vt[b][h]
// r = l*64 + b, one warp per row, 8 rows/block.
__global__ __launch_bounds__(256)
void tanhdot(const float* __restrict__ P, const float* __restrict__ addv,
             const float* __restrict__ Vt, float* __restrict__ S, int L) {
    int wid = threadIdx.x >> 5, lane = threadIdx.x & 31;
    size_t r = (size_t)blockIdx.x * 8 + wid;
    int b = (int)(r & 63), l = (int)(r >> 6);
    const float4* Pr = (const float4*)(P + r * 256);
    const float4* Vr = (const float4*)(Vt + b * 256);
    const float4* Ar = addv ? (const float4*)(addv + b * 256) : nullptr;
    float acc = 0.f;
    #pragma unroll
    for (int i = 0; i < 2; i++) {
        int c = lane + i * 32;
        float4 p = Pr[c];
        float4 v = Vr[c];
        if (Ar) { float4 a = Ar[c]; p.x += a.x; p.y += a.y; p.z += a.z; p.w += a.w; }
        acc += tanhf(p.x) * v.x + tanhf(p.y) * v.y + tanhf(p.z) * v.z + tanhf(p.w) * v.w;
    }
    #pragma unroll
    for (int o = 16; o; o >>= 1) acc += __shfl_xor_sync(0xffffffffu, acc, o);
    if (lane == 0) S[(size_t)b * L + l] = acc;
}

// ---------------- question softmax + rQ ----------------
__global__ __launch_bounds__(256)
void softq_rq(const float* __restrict__ sQ, const float* __restrict__ quesEnc,
              float* __restrict__ rQ) {
    int b = blockIdx.x, tid = threadIdx.x;
    __shared__ float a[64];
    if (tid < 64) a[tid] = sQ[b * 64 + tid];
    __syncthreads();
    if (tid == 0) {
        float m = -1e30f;
        for (int q = 0; q < 64; q++) m = fmaxf(m, a[q]);
        float s = 0.f;
        for (int q = 0; q < 64; q++) { a[q] = expf(a[q] - m); s += a[q]; }
        float inv = 1.f / s;
        for (int q = 0; q < 64; q++) a[q] *= inv;
    }
    __syncthreads();
    #pragma unroll
    for (int dd = 0; dd < 2; dd++) {
        int d = tid + dd * 256;
        float acc = 0.f;
        for (int q = 0; q < 64; q++)
            acc += a[q] * quesEnc[(size_t)(q * 64 + b) * 512 + d];
        rQ[b * 512 + d] = acc;
    }
}

// ---------------- small linear: out[b][h] = x[b][:512] . Wm[h][:512] + bv[h]
__global__ __launch_bounds__(256)
void linH(const float* __restrict__ x, const float* __restrict__ Wm,
          const float* __restrict__ bv, float* __restrict__ out) {
    int b = blockIdx.x, h = threadIdx.x;
    __shared__ float xs[512];
    xs[h] = x[b * 512 + h];
    xs[h + 256] = x[b * 512 + 256 + h];
    __syncthreads();
    float acc = bv[h];
    const float* w = Wm + (size_t)h * 512;
    #pragma unroll 8
    for (int k = 0; k < 512; k++) acc += xs[k] * w[k];
    out[b * 256 + h] = acc;
}

// ---------------- passage softmax (2048-wide), writes aP to out (+ scratch) --
__global__ __launch_bounds__(512)
void softp(const float* __restrict__ sP, float* __restrict__ outAP,
           float* __restrict__ aStore) {
    int b = blockIdx.x, tid = threadIdx.x;
    __shared__ float red[32];
    float v[4];
    float m = -1e30f;
    #pragma unroll
    for (int i = 0; i < 4; i++) {
        v[i] = sP[(size_t)b * 2048 + tid + i * 512];
        m = fmaxf(m, v[i]);
    }
    // block max
    #pragma unroll
    for (int o = 16; o; o >>= 1) m = fmaxf(m, __shfl_xor_sync(0xffffffffu, m, o));
    if ((tid & 31) == 0) red[tid >> 5] = m;
    __syncthreads();
    if (tid < 32) {
        float x = (tid < 16) ? red[tid] : -1e30f;
        #pragma unroll
        for (int o = 8; o; o >>= 1) x = fmaxf(x, __shfl_xor_sync(0xffffffffu, x, o));
        if (tid == 0) red[0] = x;
    }
    __syncthreads();
    m = red[0];
    __syncthreads();
    float s = 0.f;
    #pragma unroll
    for (int i = 0; i < 4; i++) { v[i] = expf(v[i] - m); s += v[i]; }
    #pragma unroll
    for (int o = 16; o; o >>= 1) s += __shfl_xor_sync(0xffffffffu, s, o);
    if ((tid & 31) == 0) red[tid >> 5] = s;
    __syncthreads();
    if (tid < 32) {
        float x = (tid < 16) ? red[tid] : 0.f;
        #pragma unroll
        for (int o = 8; o; o >>= 1) x += __shfl_xor_sync(0xffffffffu, x, o);
        if (tid == 0) red[0] = x;
    }
    __syncthreads();
    float inv = 1.f / red[0];
    #pragma unroll
    for (int i = 0; i < 4; i++) {
        float av = v[i] * inv;
        size_t idx = (size_t)b * 2048 + tid + i * 512;
        outAP[idx] = av;
        if (aStore) aStore[idx] = av;
    }
}

// ---------------- ct partial: per (b, slice of 128 p) -----------------------
__global__ __launch_bounds__(512)
void ct_part(const float* __restrict__ aP, const float* __restrict__ passEnc,
             float* __restrict__ part) {
    int b = blockIdx.x & 63, sl = blockIdx.x >> 6;
    int d = threadIdx.x;
    __shared__ float as[128];
    if (d < 128) as[d] = aP[(size_t)b * 2048 + sl * 128 + d];
    __syncthreads();
    float acc = 0.f;
    int p0 = sl * 128;
    for (int i = 0; i < 128; i++)
        acc += as[i] * passEnc[(size_t)((p0 + i) * 64 + b) * 512 + d];
    part[(size_t)(sl * 64 + b) * 512 + d] = acc;
}

__global__ __launch_bounds__(512)
void ct_red(const float* __restrict__ part, float* __restrict__ ct) {
    int b = blockIdx.x, d = threadIdx.x;
    float acc = 0.f;
    #pragma unroll
    for (int s = 0; s < 16; s++) acc += part[(size_t)(s * 64 + b) * 512 + d];
    ct[b * 512 + d] = acc;
}

// ---------------- GRU gate matmuls ------------------------------------------
__global__ __launch_bounds__(256)
void gru_mm(const float* __restrict__ rQ, const float* __restrict__ ct,
            const float* __restrict__ wih, const float* __restrict__ whh,
            const float* __restrict__ bih, const float* __restrict__ bhh,
            float* __restrict__ gi, float* __restrict__ gh) {
    int b = blockIdx.x & 63, part = blockIdx.x >> 6; // 0..11
    int tid = threadIdx.x;
    __shared__ float xs[512];
    const float* x  = (part < 6) ? rQ  : ct;
    const float* Wm = (part < 6) ? wih : whh;
    const float* bb = (part < 6) ? bih : bhh;
    float* o        = (part < 6) ? gi  : gh;
    int ch = (part < 6) ? part : part - 6;
    xs[tid] = x[b * 512 + tid];
    xs[tid + 256] = x[b * 512 + 256 + tid];
    __syncthreads();
    int row = ch * 256 + tid;
    float acc = bb[row];
    const float* w = Wm + (size_t)row * 512;
    #pragma unroll 8
    for (int k = 0; k < 512; k++) acc += xs[k] * w[k];
    o[(size_t)b * 1536 + row] = acc;
}

__global__ __launch_bounds__(512)
void gru_comb(const float* __restrict__ gi, const float* __restrict__ gh,
              const float* __restrict__ ct, float* __restrict__ rQ2) {
    int b = blockIdx.x, d = threadIdx.x;
    const float* gib = gi + (size_t)b * 1536;
    const float* ghb = gh + (size_t)b * 1536;
    float r = 1.f / (1.f + expf(-(gib[d] + ghb[d])));
    float z = 1.f / (1.f + expf(-(gib[512 + d] + ghb[512 + d])));
    float n = tanhf(gib[1024 + d] + r * ghb[1024 + d]);
    rQ2[b * 512 + d] = (1.f - z) * n + z * ct[b * 512 + d];
}

// ---------------- host ----------------
extern "C" void kernel_launch(void* const* d_in, const int* in_sizes, int n_in,
                              void* d_out, int out_size) {
    const float* passEnc = (const float*)d_in[0];
    const float* quesEnc = (const float*)d_in[1];
    const float* WQu_W   = (const float*)d_in[2];
    const float* WQu_b   = (const float*)d_in[3];
    const float* WQv_W   = (const float*)d_in[4];
    const float* WQv_b   = (const float*)d_in[5];
    const float* WPh_W   = (const float*)d_in[6];
    const float* WPh_b   = (const float*)d_in[7];
    const float* Wah_W   = (const float*)d_in[8];
    const float* Wah_b   = (const float*)d_in[9];
    const float* Vt1     = (const float*)d_in[10];
    const float* Vt2     = (const float*)d_in[11];
    const float* VQr     = (const float*)d_in[12];
    const float* gru_wih = (const float*)d_in[13];
    const float* gru_whh = (const float*)d_in[14];
    const float* gru_bih = (const float*)d_in[15];
    const float* gru_bhh = (const float*)d_in[16];
    float* out = (float*)d_out;

    Scratch* s = nullptr;
    cudaGetSymbolAddress((void**)&s, g_s);
    cudaFuncSetAttribute(gemm_tf32, cudaFuncAttributeMaxDynamicSharedMemorySize, GEMM_SMEM);

    // --- question path ---
    biasq_kernel<<<1, 256>>>(WQv_W, WQv_b, WQu_b, VQr);
    gemm_tf32<<<64, 256, GEMM_SMEM>>>(quesEnc, WQu_W, s->biasQ, s->quesP);
    tanhdot<<<512, 256>>>(s->quesP, nullptr, Vt1, s->sQ, 64);
    softq_rq<<<64, 256>>>(s->sQ, quesEnc, s->rQ);

    // --- passage projection (big GEMM) ---
    gemm_tf32<<<2048, 256, GEMM_SMEM>>>(passEnc, WPh_W, WPh_b, s->passP);

    // --- pointer step 1 ---
    linH<<<64, 256>>>(s->rQ, Wah_W, Wah_b, s->uah);
    tanhdot<<<16384, 256>>>(s->passP, s->uah, Vt2, s->sP, 2048);
    softp<<<64, 512>>>(s->sP, out, s->sP);          // aP1 -> out[0:131072], sP in-place = aP1
    ct_part<<<1024, 512>>>(s->sP, passEnc, s->part);
    ct_red<<<64, 512>>>(s->part, s->ct);

    // --- GRU ---
    gru_mm<<<768, 256>>>(s->rQ, s->ct, gru_wih, gru_whh, gru_bih, gru_bhh, s->gi, s->gh);
    gru_comb<<<64, 512>>>(s->gi, s->gh, s->ct, s->rQ2);

    // --- pointer step 2 ---
    linH<<<64, 256>>>(s->rQ2, Wah_W, Wah_b, s->uah);
    tanhdot<<<16384, 256>>>(s->passP, s->uah, Vt2, s->sP, 2048);
    softp<<<64, 512>>>(s->sP, out + 64 * 2048, nullptr);   // aP2
}

// round 17
// speedup vs baseline: 1.0039x; 1.0039x over previous
#include <cuda_runtime.h>
#include <cuda_bf16.h>
#include <stdint.h>

#define Hh   256
#define Bb   64
#define LPp  2048
#define LQq  64
#define D2   512
#define G3   1536

// ---------------- device scratch (no allocations allowed) ----------------
struct Scratch {
    float passP[LPp * Bb * Hh];   // [ (p*64+b) ][256]
    float quesP[LQq * Bb * Hh];   // [ (q*64+b) ][256]
    float biasQ[Hh];
    float sQ[Bb * LQq];           // [b][q]
    float rQ[Bb * D2];
    float rQ2[Bb * D2];
    float uah[Bb * Hh];
    float sP[Bb * LPp];           // [b][p] (reused in-place as aP)
    float ct[Bb * D2];
    float part[16 * Bb * D2];
    float gi[Bb * G3];
    float gh[Bb * G3];
};
__device__ Scratch g_s;

// ---------------- helpers ----------------
__device__ __forceinline__ unsigned f2tf32(float f) {
    unsigned r; asm("cvt.rna.tf32.f32 %0, %1;" : "=r"(r) : "f"(f)); return r;
}
__device__ __forceinline__ void mma8(float* c, unsigned a0, unsigned a1, unsigned a2,
                                     unsigned a3, unsigned b0, unsigned b1) {
    asm volatile(
        "mma.sync.aligned.m16n8k8.row.col.f32.tf32.tf32.f32 "
        "{%0,%1,%2,%3}, {%4,%5,%6,%7}, {%8,%9}, {%0,%1,%2,%3};"
        : "+f"(c[0]), "+f"(c[1]), "+f"(c[2]), "+f"(c[3])
        : "r"(a0), "r"(a1), "r"(a2), "r"(a3), "r"(b0), "r"(b1));
}
__device__ __forceinline__ void cp16(float* s, const float* g) {
    unsigned sa = (unsigned)__cvta_generic_to_shared(s);
    asm volatile("cp.async.cg.shared.global [%0], [%1], 16;" :: "r"(sa), "l"(g));
}

// ---------------- K0: biasQ = WQu_b + WQv_b + WQv_W @ VQr ----------------
__global__ void biasq_kernel(const float* __restrict__ WQv_W, const float* __restrict__ WQv_b,
                             const float* __restrict__ WQu_b, const float* __restrict__ VQr) {
    __shared__ float v[256];
    int tid = threadIdx.x;
    v[tid] = VQr[tid];
    __syncthreads();
    float acc = WQv_b[tid] + WQu_b[tid];
    const float* w = WQv_W + tid * 256;
    #pragma unroll 8
    for (int k = 0; k < 256; ++k) acc += w[k] * v[k];
    g_s.biasQ[tid] = acc;
}

// ---------------- tf32 GEMM: C[r][n] = A[r][:512] . W[n][:512] + bias[n] ----
// M = grid.x*64, N=256, K=512. BM=64, BN=256, BK=32. 256 thr = 8 warps (2x4).
#define SROW 36
#define A_WORDS (64 * SROW)
#define W_WORDS (256 * SROW)
#define BUFW (A_WORDS + W_WORDS)
#define GEMM_SMEM (2 * BUFW * 4)

__global__ __launch_bounds__(256, 1)
void gemm_tf32(const float* __restrict__ A, const float* __restrict__ W,
               const float* __restrict__ bias, float* __restrict__ C) {
    extern __shared__ float sm[];
    const int tid = threadIdx.x;
    const int lane = tid & 31, wid = tid >> 5;
    const int g = lane >> 2, t = lane & 3;
    const int warp_m = wid & 1;     // rows warp_m*32 .. +31
    const int warp_n = wid >> 1;    // cols warp_n*64 .. +63
    const size_t r0 = (size_t)blockIdx.x * 64;
    const float* Ag = A + r0 * 512;

    float acc[2][8][4];
    #pragma unroll
    for (int i = 0; i < 2; i++)
        #pragma unroll
        for (int j = 0; j < 8; j++) {
            acc[i][j][0] = 0.f; acc[i][j][1] = 0.f; acc[i][j][2] = 0.f; acc[i][j][3] = 0.f;
        }

    auto issue = [&](int kc, int buf) {
        float* As = sm + buf * BUFW;
        float* Ws = As + A_WORDS;
        const int k0 = kc * 32;
        #pragma unroll
        for (int i = 0; i < 2; i++) {
            int idx = tid + i * 256; int row = idx >> 3, c4 = idx & 7;
            cp16(As + row * SROW + c4 * 4, Ag + (size_t)row * 512 + k0 + c4 * 4);
        }
        #pragma unroll
        for (int i = 0; i < 8; i++) {
            int idx = tid + i * 256; int row = idx >> 3, c4 = idx & 7;
            cp16(Ws + row * SROW + c4 * 4, W + (size_t)row * 512 + k0 + c4 * 4);
        }
        asm volatile("cp.async.commit_group;");
    };

    issue(0, 0);

    for (int kc = 0; kc < 16; kc++) {
        const int cur = kc & 1;
        if (kc + 1 < 16) {
            issue(kc + 1, cur ^ 1);
            asm volatile("cp.async.wait_group 1;");
        } else {
            asm volatile("cp.async.wait_group 0;");
        }
        __syncthreads();

        const float* Ab = sm + cur * BUFW;
        const float* Wb = Ab + A_WORDS;
        #pragma unroll
        for (int ks = 0; ks < 4; ks++) {
            const int kb = ks * 8;
            unsigned a[2][4];
            #pragma unroll
            for (int mt = 0; mt < 2; mt++) {
                int row = warp_m * 32 + mt * 16 + g;
                a[mt][0] = f2tf32(Ab[row * SROW + kb + t]);
                a[mt][1] = f2tf32(Ab[(row + 8) * SROW + kb + t]);
                a[mt][2] = f2tf32(Ab[row * SROW + kb + t + 4]);
                a[mt][3] = f2tf32(Ab[(row + 8) * SROW + kb + t + 4]);
            }
            #pragma unroll
            for (int nt = 0; nt < 8; nt++) {
                int n = warp_n * 64 + nt * 8 + g;
                unsigned b0 = f2tf32(Wb[n * SROW + kb + t]);
                unsigned b1 = f2tf32(Wb[n * SROW + kb + t + 4]);
                mma8(acc[0][nt], a[0][0], a[0][1], a[0][2], a[0][3], b0, b1);
                mma8(acc[1][nt], a[1][0], a[1][1], a[1][2], a[1][3], b0, b1);
            }
        }
        __syncthreads();
    }

    // epilogue
    #pragma unroll
    for (int mt = 0; mt < 2; mt++) {
        #pragma unroll
        for (int nt = 0; nt < 8; nt++) {
            size_t row = r0 + warp_m * 32 + mt * 16 + g;
            int col = warp_n * 64 + nt * 8 + 2 * t;
            float b0 = bias[col], b1 = bias[col + 1];
            C[row * 256 + col]       = acc[mt][nt][0] + b0;
            C[row * 256 + col + 1]   = acc[mt][nt][1] + b1;
            C[(row + 8) * 256 + col]     = acc[mt][nt][2] + b0;
            C[(row + 8) * 256 + col + 1] = acc[mt][nt][3] + b1;
        }
    }
}

// ---------------- tanh-dot: S[b][l] = sum_h tanh(P[r][h] + add[b][h]) * Vt[b][h]
// r = l*64 + b, one warp per row, 8 rows/block.
__global__ __launch_bounds__(256)
void tanhdot(const float* __restrict__ P, const float* __restrict__ addv,
             const float* __restrict__ Vt, float* __restrict__ S, int L) {
    int wid = threadIdx.x >> 5, lane = threadIdx.x & 31;
    size_t r = (size_t)blockIdx.x * 8 + wid;
    int b = (int)(r & 63), l = (int)(r >> 6);
    const float4* Pr = (const float4*)(P + r * 256);
    const float4* Vr = (const float4*)(Vt + b * 256);
    const float4* Ar = addv ? (const float4*)(addv + b * 256) : nullptr;
    float acc = 0.f;
    #pragma unroll
    for (int i = 0; i < 2; i++) {
        int c = lane + i * 32;
        float4 p = Pr[c];
        float4 v = Vr[c];
        if (Ar) { float4 a = Ar[c]; p.x += a.x; p.y += a.y; p.z += a.z; p.w += a.w; }
        acc += tanhf(p.x) * v.x + tanhf(p.y) * v.y + tanhf(p.z) * v.z + tanhf(p.w) * v.w;
    }
    #pragma unroll
    for (int o = 16; o; o >>= 1) acc += __shfl_xor_sync(0xffffffffu, acc, o);
    if (lane == 0) S[(size_t)b * L + l] = acc;
}

// ---------------- question softmax + rQ ----------------
__global__ __launch_bounds__(256)
void softq_rq(const float* __restrict__ sQ, const float* __restrict__ quesEnc,
              float* __restrict__ rQ) {
    int b = blockIdx.x, tid = threadIdx.x;
    __shared__ float a[64];
    if (tid < 64) a[tid] = sQ[b * 64 + tid];
    __syncthreads();
    if (tid == 0) {
        float m = -1e30f;
        for (int q = 0; q < 64; q++) m = fmaxf(m, a[q]);
        float s = 0.f;
        for (int q = 0; q < 64; q++) { a[q] = expf(a[q] - m); s += a[q]; }
        float inv = 1.f / s;
        for (int q = 0; q < 64; q++) a[q] *= inv;
    }
    __syncthreads();
    #pragma unroll
    for (int dd = 0; dd < 2; dd++) {
        int d = tid + dd * 256;
        float acc = 0.f;
        for (int q = 0; q < 64; q++)
            acc += a[q] * quesEnc[(size_t)(q * 64 + b) * 512 + d];
        rQ[b * 512 + d] = acc;
    }
}

// ---------------- small linear: out[b][h] = x[b][:512] . Wm[h][:512] + bv[h]
__global__ __launch_bounds__(256)
void linH(const float* __restrict__ x, const float* __restrict__ Wm,
          const float* __restrict__ bv, float* __restrict__ out) {
    int b = blockIdx.x, h = threadIdx.x;
    __shared__ float xs[512];
    xs[h] = x[b * 512 + h];
    xs[h + 256] = x[b * 512 + 256 + h];
    __syncthreads();
    float acc = bv[h];
    const float* w = Wm + (size_t)h * 512;
    #pragma unroll 8
    for (int k = 0; k < 512; k++) acc += xs[k] * w[k];
    out[b * 256 + h] = acc;
}

// ---------------- passage softmax (2048-wide), writes aP to out (+ scratch) --
__global__ __launch_bounds__(512)
void softp(const float* __restrict__ sP, float* __restrict__ outAP,
           float* __restrict__ aStore) {
    int b = blockIdx.x, tid = threadIdx.x;
    __shared__ float red[32];
    float v[4];
    float m = -1e30f;
    #pragma unroll
    for (int i = 0; i < 4; i++) {
        v[i] = sP[(size_t)b * 2048 + tid + i * 512];
        m = fmaxf(m, v[i]);
    }
    // block max
    #pragma unroll
    for (int o = 16; o; o >>= 1) m = fmaxf(m, __shfl_xor_sync(0xffffffffu, m, o));
    if ((tid & 31) == 0) red[tid >> 5] = m;
    __syncthreads();
    if (tid < 32) {
        float x = (tid < 16) ? red[tid] : -1e30f;
        #pragma unroll
        for (int o = 8; o; o >>= 1) x = fmaxf(x, __shfl_xor_sync(0xffffffffu, x, o));
        if (tid == 0) red[0] = x;
    }
    __syncthreads();
    m = red[0];
    __syncthreads();
    float s = 0.f;
    #pragma unroll
    for (int i = 0; i < 4; i++) { v[i] = expf(v[i] - m); s += v[i]; }
    #pragma unroll
    for (int o = 16; o; o >>= 1) s += __shfl_xor_sync(0xffffffffu, s, o);
    if ((tid & 31) == 0) red[tid >> 5] = s;
    __syncthreads();
    if (tid < 32) {
        float x = (tid < 16) ? red[tid] : 0.f;
        #pragma unroll
        for (int o = 8; o; o >>= 1) x += __shfl_xor_sync(0xffffffffu, x, o);
        if (tid == 0) red[0] = x;
    }
    __syncthreads();
    float inv = 1.f / red[0];
    #pragma unroll
    for (int i = 0; i < 4; i++) {
        float av = v[i] * inv;
        size_t idx = (size_t)b * 2048 + tid + i * 512;
        outAP[idx] = av;
        if (aStore) aStore[idx] = av;
    }
}

// ---------------- ct partial: per (b, slice of 128 p) -----------------------
__global__ __launch_bounds__(512)
void ct_part(const float* __restrict__ aP, const float* __restrict__ passEnc,
             float* __restrict__ part) {
    int b = blockIdx.x & 63, sl = blockIdx.x >> 6;
    int d = threadIdx.x;
    __shared__ float as[128];
    if (d < 128) as[d] = aP[(size_t)b * 2048 + sl * 128 + d];
    __syncthreads();
    float acc = 0.f;
    int p0 = sl * 128;
    for (int i = 0; i < 128; i++)
        acc += as[i] * passEnc[(size_t)((p0 + i) * 64 + b) * 512 + d];
    part[(size_t)(sl * 64 + b) * 512 + d] = acc;
}

__global__ __launch_bounds__(512)
void ct_red(const float* __restrict__ part, float* __restrict__ ct) {
    int b = blockIdx.x, d = threadIdx.x;
    float acc = 0.f;
    #pragma unroll
    for (int s = 0; s < 16; s++) acc += part[(size_t)(s * 64 + b) * 512 + d];
    ct[b * 512 + d] = acc;
}

// ---------------- GRU gate matmuls ------------------------------------------
__global__ __launch_bounds__(256)
void gru_mm(const float* __restrict__ rQ, const float* __restrict__ ct,
            const float* __restrict__ wih, const float* __restrict__ whh,
            const float* __restrict__ bih, const float* __restrict__ bhh,
            float* __restrict__ gi, float* __restrict__ gh) {
    int b = blockIdx.x & 63, part = blockIdx.x >> 6; // 0..11
    int tid = threadIdx.x;
    __shared__ float xs[512];
    const float* x  = (part < 6) ? rQ  : ct;
    const float* Wm = (part < 6) ? wih : whh;
    const float* bb = (part < 6) ? bih : bhh;
    float* o        = (part < 6) ? gi  : gh;
    int ch = (part < 6) ? part : part - 6;
    xs[tid] = x[b * 512 + tid];
    xs[tid + 256] = x[b * 512 + 256 + tid];
    __syncthreads();
    int row = ch * 256 + tid;
    float acc = bb[row];
    const float* w = Wm + (size_t)row * 512;
    #pragma unroll 8
    for (int k = 0; k < 512; k++) acc += xs[k] * w[k];
    o[(size_t)b * 1536 + row] = acc;
}

__global__ __launch_bounds__(512)
void gru_comb(const float* __restrict__ gi, const float* __restrict__ gh,
              const float* __restrict__ ct, float* __restrict__ rQ2) {
    int b = blockIdx.x, d = threadIdx.x;
    const float* gib = gi + (size_t)b * 1536;
    const float* ghb = gh + (size_t)b * 1536;
    float r = 1.f / (1.f + expf(-(gib[d] + ghb[d])));
    float z = 1.f / (1.f + expf(-(gib[512 + d] + ghb[512 + d])));
    float n = tanhf(gib[1024 + d] + r * ghb[1024 + d]);
    rQ2[b * 512 + d] = (1.f - z) * n + z * ct[b * 512 + d];
}

// ---------------- host ----------------
extern "C" void kernel_launch(void* const* d_in, const int* in_sizes, int n_in,
                              void* d_out, int out_size) {
    const float* passEnc = (const float*)d_in[0];
    const float* quesEnc = (const float*)d_in[1];
    const float* WQu_W   = (const float*)d_in[2];
    const float* WQu_b   = (const float*)d_in[3];
    const float* WQv_W   = (const float*)d_in[4];
    const float* WQv_b   = (const float*)d_in[5];
    const float* WPh_W   = (const float*)d_in[6];
    const float* WPh_b   = (const float*)d_in[7];
    const float* Wah_W   = (const float*)d_in[8];
    const float* Wah_b   = (const float*)d_in[9];
    const float* Vt1     = (const float*)d_in[10];
    const float* Vt2     = (const float*)d_in[11];
    const float* VQr     = (const float*)d_in[12];
    const float* gru_wih = (const float*)d_in[13];
    const float* gru_whh = (const float*)d_in[14];
    const float* gru_bih = (const float*)d_in[15];
    const float* gru_bhh = (const float*)d_in[16];
    float* out = (float*)d_out;

    Scratch* s = nullptr;
    cudaGetSymbolAddress((void**)&s, g_s);
    cudaFuncSetAttribute(gemm_tf32, cudaFuncAttributeMaxDynamicSharedMemorySize, GEMM_SMEM);

    // --- question path ---
    biasq_kernel<<<1, 256>>>(WQv_W, WQv_b, WQu_b, VQr);
    gemm_tf32<<<64, 256, GEMM_SMEM>>>(quesEnc, WQu_W, s->biasQ, s->quesP);
    tanhdot<<<512, 256>>>(s->quesP, nullptr, Vt1, s->sQ, 64);
    softq_rq<<<64, 256>>>(s->sQ, quesEnc, s->rQ);

    // --- passage projection (big GEMM) ---
    gemm_tf32<<<2048, 256, GEMM_SMEM>>>(passEnc, WPh_W, WPh_b, s->passP);

    // --- pointer step 1 ---
    linH<<<64, 256>>>(s->rQ, Wah_W, Wah_b, s->uah);
    tanhdot<<<16384, 256>>>(s->passP, s->uah, Vt2, s->sP, 2048);
    softp<<<64, 512>>>(s->sP, out, s->sP);          // aP1 -> out[0:131072], sP in-place = aP1
    ct_part<<<1024, 512>>>(s->sP, passEnc, s->part);
    ct_red<<<64, 512>>>(s->part, s->ct);

    // --- GRU ---
    gru_mm<<<768, 256>>>(s->rQ, s->ct, gru_wih, gru_whh, gru_bih, gru_bhh, s->gi, s->gh);
    gru_comb<<<64, 512>>>(s->gi, s->gh, s->ct, s->rQ2);

    // --- pointer step 2 ---
    linH<<<64, 256>>>(s->rQ2, Wah_W, Wah_b, s->uah);
    tanhdot<<<16384, 256>>>(s->passP, s->uah, Vt2, s->sP, 2048);
    softp<<<64, 512>>>(s->sP, out + 64 * 2048, nullptr);   // aP2
}